// round 5
// baseline (speedup 1.0000x reference)
#include <cuda_runtime.h>
#include <cuda_bf16.h>

#define BB   16
#define TT   128
#define EE   512
#define HH   512
#define G4   2048      // 4*H
#define NLY  4
#define VT   32000
#define NTOK (BB*TT)   // 2048
#define NBLK 128       // recurrent grid (<=148 SMs -> all co-resident, single wave)

// ---------------- scratch (device globals; no allocs allowed) ----------------
__device__ float g_x0[NTOK*EE];         // 4MB ping
__device__ float g_x1[NTOK*EE];         // 4MB pong
__device__ float g_xW[NTOK*G4];         // 16MB gate pre-activations
__device__ float g_hbuf[2][BB*HH];      // double-buffered hidden state
__device__ float g_hN[NLY*BB*HH];       // encoder final h per layer
__device__ float g_cN[NLY*BB*HH];       // encoder final c per layer
__device__ volatile unsigned g_arrive[NBLK];  // per-block barrier generation flags

// ---------------- packed f32x2 helpers ----------------
__device__ __forceinline__ void fma2(unsigned long long &acc,
                                     unsigned long long a,
                                     unsigned long long b) {
    asm("fma.rn.f32x2 %0, %1, %2, %0;" : "+l"(acc) : "l"(a), "l"(b));
}
__device__ __forceinline__ unsigned long long dup2(float a) {
    unsigned long long r;
    asm("mov.b64 %0, {%1, %1};" : "=l"(r) : "f"(a));
    return r;
}
__device__ __forceinline__ float lo32(unsigned long long v) {
    return __uint_as_float((unsigned)v);
}
__device__ __forceinline__ float hi32(unsigned long long v) {
    return __uint_as_float((unsigned)(v >> 32));
}

// ---------------- fast grid barrier: per-block flag + all-poll ----------------
// Arrival: plain VOLATILE STORE to this block's own word (single writer per
// word -> no atomic needed; distinct words -> no L2 serialization).
// Poll: VOLATILE LOADS (ld.volatile.global) — the exact load path the proven
// R2 barrier used. (.cg polling against these lines hung twice; volatile did
// not.) Generations are monotonic across launches & graph replays: every
// launch stores base+1..base+129 into every flag, so flags are all equal at
// each kernel entry; each block reads its own flag as base.
__device__ __forceinline__ void gbar(int bk, unsigned target) {
    __syncthreads();
    if (threadIdx.x == 0) {
        __threadfence();
        g_arrive[bk] = target;          // volatile store
    }
    if (threadIdx.x < 32) {
        for (;;) {
            bool ok = true;
#pragma unroll
            for (int i = 0; i < 4; i++) {
                unsigned v = g_arrive[threadIdx.x + 32 * i];   // volatile load
                ok &= ((int)(v - target) >= 0);
            }
            if (__all_sync(0xffffffffu, ok)) break;
        }
        __threadfence();
    }
    __syncthreads();
}

// ---------------- embedding gather ----------------
__global__ void embed_kernel(const int* __restrict__ idx,
                             const float* __restrict__ emb,
                             float* __restrict__ out) {
    int row = blockIdx.x;                       // 0..2047 (b*T+t)
    int v   = idx[row];
    const float4* s = (const float4*)(emb + (size_t)v * EE);
    float4*       d = (float4*)(out + (size_t)row * EE);
    d[threadIdx.x] = s[threadIdx.x];            // 128 thr * float4 = 512
}

// ---------------- SGEMM (f32x2): C[M,N] = A[M,512] * W[N,512]^T + bias ----------------
// BM=BN=128, BK=16, 256 threads, 8x8 per thread. M,N multiples of 128, K=512.
__global__ __launch_bounds__(256)
void gemm_bias(const float* __restrict__ A,
               const float* __restrict__ W,
               const float* __restrict__ bias,
               float* __restrict__ C, int N) {
    __shared__ float As[16][132];
    __shared__ float Bs[16][132];
    const int tid = threadIdx.x;
    const int tx = tid & 15, ty = tid >> 4;
    const int n0 = blockIdx.x * 128, m0 = blockIdx.y * 128;

    unsigned long long acc[8][4];
#pragma unroll
    for (int i = 0; i < 8; i++)
#pragma unroll
        for (int j = 0; j < 4; j++) acc[i][j] = 0ull;

    for (int k0 = 0; k0 < 512; k0 += 16) {
#pragma unroll
        for (int i = 0; i < 2; i++) {
            int f4 = tid * 2 + i;               // 0..511
            int m  = f4 >> 2, kq = f4 & 3;
            float4 va = *(const float4*)&A[(size_t)(m0 + m) * 512 + k0 + kq * 4];
            As[kq*4+0][m] = va.x; As[kq*4+1][m] = va.y;
            As[kq*4+2][m] = va.z; As[kq*4+3][m] = va.w;
            float4 vb = *(const float4*)&W[(size_t)(n0 + m) * 512 + k0 + kq * 4];
            Bs[kq*4+0][m] = vb.x; Bs[kq*4+1][m] = vb.y;
            Bs[kq*4+2][m] = vb.z; Bs[kq*4+3][m] = vb.w;
        }
        __syncthreads();
#pragma unroll
        for (int kk = 0; kk < 16; kk++) {
            float4 a0 = *(const float4*)&As[kk][ty * 8];
            float4 a1 = *(const float4*)&As[kk][ty * 8 + 4];
            ulonglong2 b01 = *(const ulonglong2*)&Bs[kk][tx * 8];
            ulonglong2 b23 = *(const ulonglong2*)&Bs[kk][tx * 8 + 4];
            unsigned long long bp[4] = { b01.x, b01.y, b23.x, b23.y };
            float av[8] = { a0.x, a0.y, a0.z, a0.w, a1.x, a1.y, a1.z, a1.w };
#pragma unroll
            for (int i = 0; i < 8; i++) {
                unsigned long long ad = dup2(av[i]);
#pragma unroll
                for (int j = 0; j < 4; j++) fma2(acc[i][j], ad, bp[j]);
            }
        }
        __syncthreads();
    }

    float4 bv0 = *(const float4*)&bias[n0 + tx * 8];
    float4 bv1 = *(const float4*)&bias[n0 + tx * 8 + 4];
    float bvf[8] = { bv0.x, bv0.y, bv0.z, bv0.w, bv1.x, bv1.y, bv1.z, bv1.w };
#pragma unroll
    for (int i = 0; i < 8; i++) {
        int row = m0 + ty * 8 + i;
        float o[8];
#pragma unroll
        for (int j = 0; j < 4; j++) {
            o[2*j]   = lo32(acc[i][j]) + bvf[2*j];
            o[2*j+1] = hi32(acc[i][j]) + bvf[2*j+1];
        }
        *(float4*)&C[(size_t)row * N + n0 + tx * 8]     = make_float4(o[0], o[1], o[2], o[3]);
        *(float4*)&C[(size_t)row * N + n0 + tx * 8 + 4] = make_float4(o[4], o[5], o[6], o[7]);
    }
}

// ---------------- persistent LSTM layer ----------------
// Grid = NBLK(128) blocks x 256 threads. Block bk owns k-slice [bk*4, bk*4+4),
// i.e. 16 Whh rows (4 gates x 4 k), held in REGISTERS for all 128 steps.
// Thread (jj = tid&15, seg = tid>>4): W[jrow(jj), seg*32..seg*32+31] (32 floats).
__device__ __forceinline__ float sigmoidf_(float x) {
    return 1.0f / (1.0f + expf(-x));
}

__global__ __launch_bounds__(256)
void lstm_layer(const float* __restrict__ xW,     // [B*T, 2048]
                const float* __restrict__ Whh,    // [2048, 512]
                float* __restrict__ x_out,        // [B*T, 512]
                const float* __restrict__ h0,     // [B,512] or null->0
                const float* __restrict__ c0,     // [B,512] or null->0
                float* __restrict__ hN,           // [B,512] or null
                float* __restrict__ cN) {
    __shared__ float h_s[BB * HH];          // 32KB
    __shared__ float red[8 * 16 * 17];      // 8.5KB partial sums
    __shared__ float gpre[4][64];           // gate pre-activations
    __shared__ float c_s[4][16];            // cell state (persistent)
    __shared__ unsigned s_base;

    const int tid = threadIdx.x;
    const int bk  = blockIdx.x;
    const int jj  = tid & 15, seg = tid >> 4;
    const int k0  = bk * 4;
    const int jrow = (jj >> 2) * 512 + k0 + (jj & 3);

    if (tid == 0) s_base = g_arrive[bk];    // previous launch left all flags equal

    // Whh slice -> registers as f32x2 pairs
    unsigned long long w2[16];
    {
        const float* wr = Whh + (size_t)jrow * 512 + seg * 32;
#pragma unroll
        for (int u = 0; u < 16; u++)
            w2[u] = *reinterpret_cast<const unsigned long long*>(wr + u * 2);
    }

    // gather-phase mapping: 256 = 16(b) x 4(kx) x 4(gate)
    const int b2 = tid & 15, kx2 = (tid >> 4) & 3, q2 = tid >> 6;
    const int jjg = q2 * 4 + kx2;
    const int jrg = q2 * 512 + k0 + kx2;

    float h_last = 0.f, c_last = 0.f;
    if (tid < 64) {
        int b = tid & 15, kx = tid >> 4, k = k0 + kx;
        c_s[kx][b] = c0 ? c0[b * HH + k] : 0.f;
        g_hbuf[0][b * HH + k] = h0 ? h0[b * HH + k] : 0.f;
        __threadfence();                    // writer-side release
    }
    __syncthreads();
    unsigned base = s_base;
    unsigned barn = 0;
    gbar(bk, base + (++barn));              // publish initial h/c

    for (int t = 0; t < TT; t++) {
        // reload h (L2-coherent) into smem; read buffer = t&1
        const float4* gh4 = (const float4*)g_hbuf[t & 1];
        float4* hs4 = (float4*)h_s;
#pragma unroll
        for (int u = 0; u < 8; u++)
            hs4[tid + u * 256] = __ldcg(gh4 + tid + u * 256);
        __syncthreads();

        // partial dot: acc[b] = sum_{k in my 32} h[b,k]*W[jrow,k]
        unsigned long long acc[16];
#pragma unroll
        for (int b = 0; b < 16; b++) acc[b] = 0ull;
#pragma unroll
        for (int u = 0; u < 16; u += 2) {
            const unsigned long long wa = w2[u], wb = w2[u + 1];
#pragma unroll
            for (int b = 0; b < 16; b++) {
                ulonglong2 hv = *reinterpret_cast<const ulonglong2*>(
                    &h_s[b * HH + seg * 32 + u * 2]);
                fma2(acc[b], wa, hv.x);
                fma2(acc[b], wb, hv.y);
            }
        }
        // pair-reduce across adjacent segs via shuffle, store 8 partials
#pragma unroll
        for (int b = 0; b < 16; b++) {
            float p = lo32(acc[b]) + hi32(acc[b]);
            p += __shfl_xor_sync(0xffffffffu, p, 16);
            if ((tid & 16) == 0)
                red[((seg >> 1) * 16 + jj) * 17 + b] = p;
        }
        __syncthreads();

        // gather: full dot + xW
        float gv = xW[((size_t)b2 * TT + t) * G4 + jrg];
#pragma unroll
        for (int s = 0; s < 8; s++) gv += red[(s * 16 + jjg) * 17 + b2];
        gpre[q2][kx2 * 16 + b2] = gv;
        __syncthreads();

        // pointwise update (64 threads own the block's 16b x 4k states);
        // write NEXT h into the other buffer (race-free with 1 barrier/step:
        // a fast block can only overwrite buffer t&1 after passing the step-t
        // barrier, which requires every block to have finished reading it)
        if (tid < 64) {
            int b = tid & 15, kx = tid >> 4, k = k0 + kx;
            float iv = gpre[0][kx * 16 + b];
            float fv = gpre[1][kx * 16 + b];
            float gg = gpre[2][kx * 16 + b];
            float ov = gpre[3][kx * 16 + b];
            float cold = c_s[kx][b];
            float cn = sigmoidf_(fv) * cold + sigmoidf_(iv) * tanhf(gg);
            float hn = sigmoidf_(ov) * tanhf(cn);
            c_s[kx][b] = cn;
            h_last = hn; c_last = cn;
            g_hbuf[(t + 1) & 1][b * HH + k] = hn;
            x_out[((size_t)b * TT + t) * HH + k] = hn;
            __threadfence();                // writer-side release before flag
        }
        gbar(bk, base + (++barn));
    }

    if (hN != nullptr && tid < 64) {
        int b = tid & 15, kx = tid >> 4, k = k0 + kx;
        hN[b * HH + k] = h_last;
        cN[b * HH + k] = c_last;
    }
}

// ---------------- host orchestration ----------------
extern "C" void kernel_launch(void* const* d_in, const int* in_sizes, int n_in,
                              void* d_out, int out_size) {
    (void)in_sizes; (void)n_in; (void)out_size;
    const int*   src     = (const int*)  d_in[0];
    const int*   tgt     = (const int*)  d_in[1];
    const float* src_emb = (const float*)d_in[2];
    const float* tgt_emb = (const float*)d_in[3];
    const float* enc_Wih = (const float*)d_in[4];
    const float* enc_Whh = (const float*)d_in[5];
    const float* enc_b   = (const float*)d_in[6];
    const float* dec_Wih = (const float*)d_in[7];
    const float* dec_Whh = (const float*)d_in[8];
    const float* dec_b   = (const float*)d_in[9];
    const float* fc_W    = (const float*)d_in[10];
    const float* fc_b    = (const float*)d_in[11];
    float* out = (float*)d_out;

    float *x0, *x1, *xw, *hN, *cN;
    cudaGetSymbolAddress((void**)&x0, g_x0);
    cudaGetSymbolAddress((void**)&x1, g_x1);
    cudaGetSymbolAddress((void**)&xw, g_xW);
    cudaGetSymbolAddress((void**)&hN, g_hN);
    cudaGetSymbolAddress((void**)&cN, g_cN);

    dim3 ggemm(G4 / 128, NTOK / 128);   // 16 x 16

    // ---- encoder ----
    embed_kernel<<<NTOK, 128>>>(src, src_emb, x0);
    for (int l = 0; l < NLY; l++) {
        const float* xi = (l & 1) ? x1 : x0;
        float*       xo = (l & 1) ? x0 : x1;
        gemm_bias<<<ggemm, 256>>>(xi, enc_Wih + (size_t)l * G4 * EE,
                                  enc_b + l * G4, xw, G4);
        lstm_layer<<<NBLK, 256>>>(xw, enc_Whh + (size_t)l * G4 * HH, xo,
                                  nullptr, nullptr,
                                  hN + l * BB * HH, cN + l * BB * HH);
    }
    // ---- decoder (init from encoder finals) ----
    embed_kernel<<<NTOK, 128>>>(tgt, tgt_emb, x0);
    for (int l = 0; l < NLY; l++) {
        const float* xi = (l & 1) ? x1 : x0;
        float*       xo = (l & 1) ? x0 : x1;
        gemm_bias<<<ggemm, 256>>>(xi, dec_Wih + (size_t)l * G4 * EE,
                                  dec_b + l * G4, xw, G4);
        lstm_layer<<<NBLK, 256>>>(xw, dec_Whh + (size_t)l * G4 * HH, xo,
                                  hN + l * BB * HH, cN + l * BB * HH,
                                  nullptr, nullptr);
    }
    // ---- vocab projection (decoder layer-3 output lands in x0) ----
    gemm_bias<<<dim3(VT / 128, NTOK / 128), 256>>>(x0, fc_W, fc_b, out, VT);
}

// round 6
// speedup vs baseline: 1.4684x; 1.4684x over previous
#include <cuda_runtime.h>
#include <cuda_bf16.h>

#define BB   16
#define TT   128
#define EE   512
#define HH   512
#define G4   2048      // 4*H
#define NLY  4
#define VT   32000
#define NTOK (BB*TT)   // 2048
#define NBLK 128       // recurrent grid (<=148 SMs -> all co-resident, single wave)

// ---------------- scratch (device globals; no allocs allowed) ----------------
__device__ float g_x0[NTOK*EE];         // 4MB ping
__device__ float g_x1[NTOK*EE];         // 4MB pong
__device__ float g_xW[NTOK*G4];         // 16MB gate pre-activations
__device__ float g_hbuf[2][BB*HH];      // double-buffered hidden state
__device__ float g_hN[NLY*BB*HH];       // encoder final h per layer
__device__ float g_cN[NLY*BB*HH];       // encoder final c per layer
__device__ unsigned g_flags[NBLK * 32]; // per-block flag, each on its own 128B line
__device__ unsigned g_gen;              // master-published generation

// ---------------- packed f32x2 helpers ----------------
__device__ __forceinline__ void fma2(unsigned long long &acc,
                                     unsigned long long a,
                                     unsigned long long b) {
    asm("fma.rn.f32x2 %0, %1, %2, %0;" : "+l"(acc) : "l"(a), "l"(b));
}
__device__ __forceinline__ unsigned long long dup2(float a) {
    unsigned long long r;
    asm("mov.b64 %0, {%1, %1};" : "=l"(r) : "f"(a));
    return r;
}
__device__ __forceinline__ float lo32(unsigned long long v) {
    return __uint_as_float((unsigned)v);
}
__device__ __forceinline__ float hi32(unsigned long long v) {
    return __uint_as_float((unsigned)(v >> 32));
}

// ---------------- two-level grid barrier ----------------
// Arrival: volatile store to own flag (own 128B line -> no line sharing).
// Aggregate: ONLY block 0's warp 0 polls the 128 flags (4 lines/lane, MLP=4).
// Publish: block 0 volatile-stores g_gen; other blocks poll that single word
// with a single thread. Volatile ld/st path matches the R2 barrier that
// provably worked; total poll traffic per round is ~128 loads of 1 word plus
// 128 loads by the master, instead of R5's 16K.
// Monotonic across launches/graph replays: each launch moves every flag and
// g_gen from base to base+129; base is re-read at kernel entry.
__device__ __forceinline__ void gbar(int bk, unsigned target) {
    __syncthreads();
    if (threadIdx.x == 0) {
        __threadfence();
        *(volatile unsigned*)&g_flags[bk * 32] = target;   // arrive
    }
    if (bk == 0) {
        if (threadIdx.x < 32) {
            for (;;) {
                bool ok = true;
#pragma unroll
                for (int i = 0; i < 4; i++) {
                    unsigned v = *(volatile unsigned*)&g_flags[(threadIdx.x + 32 * i) * 32];
                    ok &= ((int)(v - target) >= 0);
                }
                if (__all_sync(0xffffffffu, ok)) break;
            }
            if (threadIdx.x == 0) {
                __threadfence();
                *(volatile unsigned*)&g_gen = target;      // publish
            }
        }
    } else {
        if (threadIdx.x == 0) {
            while ((int)(*(volatile unsigned*)&g_gen - target) < 0) {}
            __threadfence();
        }
    }
    __syncthreads();
}

// ---------------- embedding gather ----------------
__global__ void embed_kernel(const int* __restrict__ idx,
                             const float* __restrict__ emb,
                             float* __restrict__ out) {
    int row = blockIdx.x;                       // 0..2047 (b*T+t)
    int v   = idx[row];
    const float4* s = (const float4*)(emb + (size_t)v * EE);
    float4*       d = (float4*)(out + (size_t)row * EE);
    d[threadIdx.x] = s[threadIdx.x];            // 128 thr * float4 = 512
}

// ---------------- SGEMM (f32x2): C[M,N] = A[M,512] * W[N,512]^T + bias ----------------
// BM=BN=128, BK=16, 256 threads, 8x8 per thread. M,N multiples of 128, K=512.
__global__ __launch_bounds__(256)
void gemm_bias(const float* __restrict__ A,
               const float* __restrict__ W,
               const float* __restrict__ bias,
               float* __restrict__ C, int N) {
    __shared__ float As[16][132];
    __shared__ float Bs[16][132];
    const int tid = threadIdx.x;
    const int tx = tid & 15, ty = tid >> 4;
    const int n0 = blockIdx.x * 128, m0 = blockIdx.y * 128;

    unsigned long long acc[8][4];
#pragma unroll
    for (int i = 0; i < 8; i++)
#pragma unroll
        for (int j = 0; j < 4; j++) acc[i][j] = 0ull;

    for (int k0 = 0; k0 < 512; k0 += 16) {
#pragma unroll
        for (int i = 0; i < 2; i++) {
            int f4 = tid * 2 + i;               // 0..511
            int m  = f4 >> 2, kq = f4 & 3;
            float4 va = *(const float4*)&A[(size_t)(m0 + m) * 512 + k0 + kq * 4];
            As[kq*4+0][m] = va.x; As[kq*4+1][m] = va.y;
            As[kq*4+2][m] = va.z; As[kq*4+3][m] = va.w;
            float4 vb = *(const float4*)&W[(size_t)(n0 + m) * 512 + k0 + kq * 4];
            Bs[kq*4+0][m] = vb.x; Bs[kq*4+1][m] = vb.y;
            Bs[kq*4+2][m] = vb.z; Bs[kq*4+3][m] = vb.w;
        }
        __syncthreads();
#pragma unroll
        for (int kk = 0; kk < 16; kk++) {
            float4 a0 = *(const float4*)&As[kk][ty * 8];
            float4 a1 = *(const float4*)&As[kk][ty * 8 + 4];
            ulonglong2 b01 = *(const ulonglong2*)&Bs[kk][tx * 8];
            ulonglong2 b23 = *(const ulonglong2*)&Bs[kk][tx * 8 + 4];
            unsigned long long bp[4] = { b01.x, b01.y, b23.x, b23.y };
            float av[8] = { a0.x, a0.y, a0.z, a0.w, a1.x, a1.y, a1.z, a1.w };
#pragma unroll
            for (int i = 0; i < 8; i++) {
                unsigned long long ad = dup2(av[i]);
#pragma unroll
                for (int j = 0; j < 4; j++) fma2(acc[i][j], ad, bp[j]);
            }
        }
        __syncthreads();
    }

    float4 bv0 = *(const float4*)&bias[n0 + tx * 8];
    float4 bv1 = *(const float4*)&bias[n0 + tx * 8 + 4];
    float bvf[8] = { bv0.x, bv0.y, bv0.z, bv0.w, bv1.x, bv1.y, bv1.z, bv1.w };
#pragma unroll
    for (int i = 0; i < 8; i++) {
        int row = m0 + ty * 8 + i;
        float o[8];
#pragma unroll
        for (int j = 0; j < 4; j++) {
            o[2*j]   = lo32(acc[i][j]) + bvf[2*j];
            o[2*j+1] = hi32(acc[i][j]) + bvf[2*j+1];
        }
        *(float4*)&C[(size_t)row * N + n0 + tx * 8]     = make_float4(o[0], o[1], o[2], o[3]);
        *(float4*)&C[(size_t)row * N + n0 + tx * 8 + 4] = make_float4(o[4], o[5], o[6], o[7]);
    }
}

// ---------------- persistent LSTM layer ----------------
// Grid = NBLK(128) blocks x 256 threads. Block bk owns k-slice [bk*4, bk*4+4),
// i.e. 16 Whh rows (4 gates x 4 k), held in REGISTERS for all 128 steps.
// Thread (jj = tid&15, seg = tid>>4): W[jrow(jj), seg*32..seg*32+31] (32 floats).
__device__ __forceinline__ float sigmoidf_(float x) {
    return 1.0f / (1.0f + expf(-x));
}

__global__ __launch_bounds__(256)
void lstm_layer(const float* __restrict__ xW,     // [B*T, 2048]
                const float* __restrict__ Whh,    // [2048, 512]
                float* __restrict__ x_out,        // [B*T, 512]
                const float* __restrict__ h0,     // [B,512] or null->0
                const float* __restrict__ c0,     // [B,512] or null->0
                float* __restrict__ hN,           // [B,512] or null
                float* __restrict__ cN) {
    __shared__ float h_s[BB * HH];          // 32KB
    __shared__ float red[8 * 16 * 17];      // 8.5KB partial sums
    __shared__ float gpre[4][64];           // gate pre-activations
    __shared__ float c_s[4][16];            // cell state (persistent)
    __shared__ unsigned s_base;

    const int tid = threadIdx.x;
    const int bk  = blockIdx.x;
    const int jj  = tid & 15, seg = tid >> 4;
    const int k0  = bk * 4;
    const int jrow = (jj >> 2) * 512 + k0 + (jj & 3);

    if (tid == 0) s_base = *(volatile unsigned*)&g_flags[bk * 32];

    // Whh slice -> registers as f32x2 pairs
    unsigned long long w2[16];
    {
        const float* wr = Whh + (size_t)jrow * 512 + seg * 32;
#pragma unroll
        for (int u = 0; u < 16; u++)
            w2[u] = *reinterpret_cast<const unsigned long long*>(wr + u * 2);
    }

    // gather-phase mapping: 256 = 16(b) x 4(kx) x 4(gate)
    const int b2 = tid & 15, kx2 = (tid >> 4) & 3, q2 = tid >> 6;
    const int jjg = q2 * 4 + kx2;
    const int jrg = q2 * 512 + k0 + kx2;

    float h_last = 0.f, c_last = 0.f;
    if (tid < 64) {
        int b = tid & 15, kx = tid >> 4, k = k0 + kx;
        c_s[kx][b] = c0 ? c0[b * HH + k] : 0.f;
        g_hbuf[0][b * HH + k] = h0 ? h0[b * HH + k] : 0.f;
    }
    __syncthreads();
    unsigned base = s_base;
    unsigned barn = 0;
    gbar(bk, base + (++barn));              // publish initial h/c

    for (int t = 0; t < TT; t++) {
        // reload h (L2-coherent) into smem; read buffer = t&1
        const float4* gh4 = (const float4*)g_hbuf[t & 1];
        float4* hs4 = (float4*)h_s;
#pragma unroll
        for (int u = 0; u < 8; u++)
            hs4[tid + u * 256] = __ldcg(gh4 + tid + u * 256);
        __syncthreads();

        // partial dot: acc[b] = sum_{k in my 32} h[b,k]*W[jrow,k]
        unsigned long long acc[16];
#pragma unroll
        for (int b = 0; b < 16; b++) acc[b] = 0ull;
#pragma unroll
        for (int u = 0; u < 16; u += 2) {
            const unsigned long long wa = w2[u], wb = w2[u + 1];
#pragma unroll
            for (int b = 0; b < 16; b++) {
                ulonglong2 hv = *reinterpret_cast<const ulonglong2*>(
                    &h_s[b * HH + seg * 32 + u * 2]);
                fma2(acc[b], wa, hv.x);
                fma2(acc[b], wb, hv.y);
            }
        }
        // pair-reduce across adjacent segs via shuffle, store 8 partials
#pragma unroll
        for (int b = 0; b < 16; b++) {
            float p = lo32(acc[b]) + hi32(acc[b]);
            p += __shfl_xor_sync(0xffffffffu, p, 16);
            if ((tid & 16) == 0)
                red[((seg >> 1) * 16 + jj) * 17 + b] = p;
        }
        __syncthreads();

        // gather: full dot + xW
        float gv = xW[((size_t)b2 * TT + t) * G4 + jrg];
#pragma unroll
        for (int s = 0; s < 8; s++) gv += red[(s * 16 + jjg) * 17 + b2];
        gpre[q2][kx2 * 16 + b2] = gv;
        __syncthreads();

        // pointwise update (64 threads own the block's 16b x 4k states);
        // write NEXT h into the other buffer (race-free with 1 barrier/step:
        // a fast block can only overwrite buffer t&1 after passing the step-t
        // barrier, which requires every block to have finished reading it)
        if (tid < 64) {
            int b = tid & 15, kx = tid >> 4, k = k0 + kx;
            float iv = gpre[0][kx * 16 + b];
            float fv = gpre[1][kx * 16 + b];
            float gg = gpre[2][kx * 16 + b];
            float ov = gpre[3][kx * 16 + b];
            float cold = c_s[kx][b];
            float cn = sigmoidf_(fv) * cold + sigmoidf_(iv) * tanhf(gg);
            float hn = sigmoidf_(ov) * tanhf(cn);
            c_s[kx][b] = cn;
            h_last = hn; c_last = cn;
            g_hbuf[(t + 1) & 1][b * HH + k] = hn;
            x_out[((size_t)b * TT + t) * HH + k] = hn;
        }
        gbar(bk, base + (++barn));
    }

    if (hN != nullptr && tid < 64) {
        int b = tid & 15, kx = tid >> 4, k = k0 + kx;
        hN[b * HH + k] = h_last;
        cN[b * HH + k] = c_last;
    }
}

// ---------------- host orchestration ----------------
extern "C" void kernel_launch(void* const* d_in, const int* in_sizes, int n_in,
                              void* d_out, int out_size) {
    (void)in_sizes; (void)n_in; (void)out_size;
    const int*   src     = (const int*)  d_in[0];
    const int*   tgt     = (const int*)  d_in[1];
    const float* src_emb = (const float*)d_in[2];
    const float* tgt_emb = (const float*)d_in[3];
    const float* enc_Wih = (const float*)d_in[4];
    const float* enc_Whh = (const float*)d_in[5];
    const float* enc_b   = (const float*)d_in[6];
    const float* dec_Wih = (const float*)d_in[7];
    const float* dec_Whh = (const float*)d_in[8];
    const float* dec_b   = (const float*)d_in[9];
    const float* fc_W    = (const float*)d_in[10];
    const float* fc_b    = (const float*)d_in[11];
    float* out = (float*)d_out;

    float *x0, *x1, *xw, *hN, *cN;
    cudaGetSymbolAddress((void**)&x0, g_x0);
    cudaGetSymbolAddress((void**)&x1, g_x1);
    cudaGetSymbolAddress((void**)&xw, g_xW);
    cudaGetSymbolAddress((void**)&hN, g_hN);
    cudaGetSymbolAddress((void**)&cN, g_cN);

    dim3 ggemm(G4 / 128, NTOK / 128);   // 16 x 16

    // ---- encoder ----
    embed_kernel<<<NTOK, 128>>>(src, src_emb, x0);
    for (int l = 0; l < NLY; l++) {
        const float* xi = (l & 1) ? x1 : x0;
        float*       xo = (l & 1) ? x0 : x1;
        gemm_bias<<<ggemm, 256>>>(xi, enc_Wih + (size_t)l * G4 * EE,
                                  enc_b + l * G4, xw, G4);
        lstm_layer<<<NBLK, 256>>>(xw, enc_Whh + (size_t)l * G4 * HH, xo,
                                  nullptr, nullptr,
                                  hN + l * BB * HH, cN + l * BB * HH);
    }
    // ---- decoder (init from encoder finals) ----
    embed_kernel<<<NTOK, 128>>>(tgt, tgt_emb, x0);
    for (int l = 0; l < NLY; l++) {
        const float* xi = (l & 1) ? x1 : x0;
        float*       xo = (l & 1) ? x0 : x1;
        gemm_bias<<<ggemm, 256>>>(xi, dec_Wih + (size_t)l * G4 * EE,
                                  dec_b + l * G4, xw, G4);
        lstm_layer<<<NBLK, 256>>>(xw, dec_Whh + (size_t)l * G4 * HH, xo,
                                  hN + l * BB * HH, cN + l * BB * HH,
                                  nullptr, nullptr);
    }
    // ---- vocab projection (decoder layer-3 output lands in x0) ----
    gemm_bias<<<dim3(VT / 128, NTOK / 128), 256>>>(x0, fc_W, fc_b, out, VT);
}

// round 8
// speedup vs baseline: 1.7388x; 1.1842x over previous
#include <cuda_runtime.h>
#include <cuda_bf16.h>
#include <cstdint>

#define BB   16
#define TT   128
#define EE   512
#define HH   512
#define G4   2048      // 4*H
#define NLY  4
#define VT   32000
#define NTOK (BB*TT)   // 2048
#define NBLK 128       // recurrent grid

// ---------------- scratch (device globals; no allocs allowed) ----------------
__device__ float g_x0[NTOK*EE];
__device__ float g_x1[NTOK*EE];
__device__ float g_xW[NTOK*G4];
__device__ float g_hbuf[2][BB*HH];
__device__ float g_hN[NLY*BB*HH];
__device__ float g_cN[NLY*BB*HH];
__device__ unsigned g_flags[NBLK * 32];
__device__ unsigned g_gen;
// bf16 split buffers
__device__ __nv_bfloat16 g_ahi[NTOK*EE], g_alo[NTOK*EE];
__device__ __nv_bfloat16 g_whi[G4*EE],  g_wlo[G4*EE];
__device__ __nv_bfloat16 g_fwhi[VT*EE], g_fwlo[VT*EE];

// ---------------- fp32 -> bf16 hi/lo split ----------------
__global__ void split_kernel(const float* __restrict__ in,
                             __nv_bfloat16* __restrict__ hi,
                             __nv_bfloat16* __restrict__ lo, int n4) {
    int i = blockIdx.x * blockDim.x + threadIdx.x;
    if (i >= n4) return;
    float4 v = ((const float4*)in)[i];
    __nv_bfloat16 h[4], l[4];
    float f[4] = { v.x, v.y, v.z, v.w };
#pragma unroll
    for (int j = 0; j < 4; j++) {
        h[j] = __float2bfloat16(f[j]);
        l[j] = __float2bfloat16(f[j] - __bfloat162float(h[j]));
    }
    ((uint2*)hi)[i] = *(uint2*)h;
    ((uint2*)lo)[i] = *(uint2*)l;
}

// ---------------- mma.sync helper ----------------
__device__ __forceinline__ void mma16816(float* d, const uint32_t* a, const uint32_t* b) {
    asm volatile(
        "mma.sync.aligned.m16n8k16.row.col.f32.bf16.bf16.f32 "
        "{%0,%1,%2,%3}, {%4,%5,%6,%7}, {%8,%9}, {%0,%1,%2,%3};"
        : "+f"(d[0]), "+f"(d[1]), "+f"(d[2]), "+f"(d[3])
        : "r"(a[0]), "r"(a[1]), "r"(a[2]), "r"(a[3]), "r"(b[0]), "r"(b[1]));
}

// ---------------- bf16 split GEMM via mma.sync ----------------
// C[M,N] = A[M,512]*W[N,512]^T + bias, 3-term split in fp32 accum.
// Block tile 128x128, 8 warps (2m x 4n), warp tile 64x32, K-chunk 64.
// smem: 4 tiles of 128 rows x 36 words (row = 64 bf16 padded to 72). 72KB.
#define SMW 36                         // words per smem row
#define TILE_WORDS (128 * SMW)         // 4608 words = 18KB
__global__ __launch_bounds__(256)
void gemm_mma(const __nv_bfloat16* __restrict__ Ahi, const __nv_bfloat16* __restrict__ Alo,
              const __nv_bfloat16* __restrict__ Bhi, const __nv_bfloat16* __restrict__ Blo,
              const float* __restrict__ bias, float* __restrict__ C, int N) {
    extern __shared__ uint32_t sm[];
    uint32_t* sAhi = sm;
    uint32_t* sAlo = sm + TILE_WORDS;
    uint32_t* sBhi = sm + 2 * TILE_WORDS;
    uint32_t* sBlo = sm + 3 * TILE_WORDS;

    const int tid  = threadIdx.x;
    const int lane = tid & 31;
    const int wid  = tid >> 5;
    const int n0 = blockIdx.x * 128, m0 = blockIdx.y * 128;
    const int m0w = (wid & 1) * 64;            // warp m offset in tile
    const int n0w = (wid >> 1) * 32;           // warp n offset in tile

    const int lr = lane >> 2;                  // 0..7 row-in-frag
    const int lc = lane & 3;                   // 0..3 k-word-in-frag

    float acc[4][4][4];
#pragma unroll
    for (int i = 0; i < 4; i++)
#pragma unroll
        for (int j = 0; j < 4; j++)
#pragma unroll
            for (int q = 0; q < 4; q++) acc[i][j][q] = 0.f;

    for (int kc = 0; kc < 8; kc++) {
        const int k0 = kc * 64;
        // load 4 tiles: 128 rows x 64 bf16 each, global row stride 512
        {
            const __nv_bfloat16* srcs[4] = {
                Ahi + (size_t)m0 * 512 + k0, Alo + (size_t)m0 * 512 + k0,
                Bhi + (size_t)n0 * 512 + k0, Blo + (size_t)n0 * 512 + k0 };
            uint32_t* dsts[4] = { sAhi, sAlo, sBhi, sBlo };
#pragma unroll
            for (int tl = 0; tl < 4; tl++) {
#pragma unroll
                for (int i = 0; i < 4; i++) {
                    int lin = tid + i * 256;       // 0..1023
                    int row = lin >> 3, g = lin & 7;
                    uint4 v = *(const uint4*)(srcs[tl] + (size_t)row * 512 + g * 8);
                    uint32_t* d = dsts[tl] + row * SMW + g * 4;
                    *(uint2*)d       = make_uint2(v.x, v.y);
                    *(uint2*)(d + 2) = make_uint2(v.z, v.w);
                }
            }
        }
        __syncthreads();

#pragma unroll
        for (int kk = 0; kk < 4; kk++) {
            const int kw = kk * 8 + lc;            // word index in row
            uint32_t ah[4][4], al[4][4], bh[4][2], bl[4][2];
#pragma unroll
            for (int mt = 0; mt < 4; mt++) {
                int r = m0w + mt * 16 + lr;
                ah[mt][0] = sAhi[r * SMW + kw];
                ah[mt][1] = sAhi[(r + 8) * SMW + kw];
                ah[mt][2] = sAhi[r * SMW + kw + 4];
                ah[mt][3] = sAhi[(r + 8) * SMW + kw + 4];
                al[mt][0] = sAlo[r * SMW + kw];
                al[mt][1] = sAlo[(r + 8) * SMW + kw];
                al[mt][2] = sAlo[r * SMW + kw + 4];
                al[mt][3] = sAlo[(r + 8) * SMW + kw + 4];
            }
#pragma unroll
            for (int nt = 0; nt < 4; nt++) {
                int n = n0w + nt * 8 + lr;
                bh[nt][0] = sBhi[n * SMW + kw];
                bh[nt][1] = sBhi[n * SMW + kw + 4];
                bl[nt][0] = sBlo[n * SMW + kw];
                bl[nt][1] = sBlo[n * SMW + kw + 4];
            }
#pragma unroll
            for (int mt = 0; mt < 4; mt++)
#pragma unroll
                for (int nt = 0; nt < 4; nt++) {
                    mma16816(acc[mt][nt], ah[mt], bh[nt]);
                    mma16816(acc[mt][nt], ah[mt], bl[nt]);
                    mma16816(acc[mt][nt], al[mt], bh[nt]);
                }
        }
        __syncthreads();
    }

    // epilogue: acc frag (m16n8): c0,c1 -> row lr, cols lc*2+{0,1}; c2,c3 -> row lr+8
#pragma unroll
    for (int nt = 0; nt < 4; nt++) {
        int col = n0 + n0w + nt * 8 + lc * 2;
        float2 bv = *(const float2*)&bias[col];
#pragma unroll
        for (int mt = 0; mt < 4; mt++) {
            int r = m0 + m0w + mt * 16 + lr;
            *(float2*)&C[(size_t)r * N + col] =
                make_float2(acc[mt][nt][0] + bv.x, acc[mt][nt][1] + bv.y);
            *(float2*)&C[(size_t)(r + 8) * N + col] =
                make_float2(acc[mt][nt][2] + bv.x, acc[mt][nt][3] + bv.y);
        }
    }
}
#define GEMM_SMEM (4 * TILE_WORDS * 4)   // 73728 bytes

// ---------------- embedding gather ----------------
__global__ void embed_kernel(const int* __restrict__ idx,
                             const float* __restrict__ emb,
                             float* __restrict__ out) {
    int row = blockIdx.x;
    int v   = idx[row];
    const float4* s = (const float4*)(emb + (size_t)v * EE);
    float4*       d = (float4*)(out + (size_t)row * EE);
    d[threadIdx.x] = s[threadIdx.x];
}

// ---------------- packed f32x2 helpers (LSTM) ----------------
__device__ __forceinline__ void fma2(unsigned long long &acc,
                                     unsigned long long a, unsigned long long b) {
    asm("fma.rn.f32x2 %0, %1, %2, %0;" : "+l"(acc) : "l"(a), "l"(b));
}
__device__ __forceinline__ float lo32(unsigned long long v) { return __uint_as_float((unsigned)v); }
__device__ __forceinline__ float hi32(unsigned long long v) { return __uint_as_float((unsigned)(v >> 32)); }

// ---------------- two-level grid barrier (proven R6) ----------------
__device__ __forceinline__ void gbar(int bk, unsigned target) {
    __syncthreads();
    if (threadIdx.x == 0) {
        __threadfence();
        *(volatile unsigned*)&g_flags[bk * 32] = target;
    }
    if (bk == 0) {
        if (threadIdx.x < 32) {
            for (;;) {
                bool ok = true;
#pragma unroll
                for (int i = 0; i < 4; i++) {
                    unsigned v = *(volatile unsigned*)&g_flags[(threadIdx.x + 32 * i) * 32];
                    ok &= ((int)(v - target) >= 0);
                }
                if (__all_sync(0xffffffffu, ok)) break;
            }
            if (threadIdx.x == 0) {
                __threadfence();
                *(volatile unsigned*)&g_gen = target;
            }
        }
    } else {
        if (threadIdx.x == 0) {
            while ((int)(*(volatile unsigned*)&g_gen - target) < 0) {}
            __threadfence();
        }
    }
    __syncthreads();
}

__device__ __forceinline__ float sigmoidf_(float x) { return 1.0f / (1.0f + expf(-x)); }

// ---------------- persistent LSTM layer (unchanged from R6) ----------------
__global__ __launch_bounds__(256)
void lstm_layer(const float* __restrict__ xW, const float* __restrict__ Whh,
                float* __restrict__ x_out,
                const float* __restrict__ h0, const float* __restrict__ c0,
                float* __restrict__ hN, float* __restrict__ cN) {
    __shared__ float h_s[BB * HH];
    __shared__ float red[8 * 16 * 17];
    __shared__ float gpre[4][64];
    __shared__ float c_s[4][16];
    __shared__ unsigned s_base;

    const int tid = threadIdx.x;
    const int bk  = blockIdx.x;
    const int jj  = tid & 15, seg = tid >> 4;
    const int k0  = bk * 4;
    const int jrow = (jj >> 2) * 512 + k0 + (jj & 3);

    if (tid == 0) s_base = *(volatile unsigned*)&g_flags[bk * 32];

    unsigned long long w2[16];
    {
        const float* wr = Whh + (size_t)jrow * 512 + seg * 32;
#pragma unroll
        for (int u = 0; u < 16; u++)
            w2[u] = *reinterpret_cast<const unsigned long long*>(wr + u * 2);
    }

    const int b2 = tid & 15, kx2 = (tid >> 4) & 3, q2 = tid >> 6;
    const int jjg = q2 * 4 + kx2;
    const int jrg = q2 * 512 + k0 + kx2;

    float h_last = 0.f, c_last = 0.f;
    if (tid < 64) {
        int b = tid & 15, kx = tid >> 4, k = k0 + kx;
        c_s[kx][b] = c0 ? c0[b * HH + k] : 0.f;
        g_hbuf[0][b * HH + k] = h0 ? h0[b * HH + k] : 0.f;
    }
    __syncthreads();
    unsigned base = s_base;
    unsigned barn = 0;
    gbar(bk, base + (++barn));

    for (int t = 0; t < TT; t++) {
        const float4* gh4 = (const float4*)g_hbuf[t & 1];
        float4* hs4 = (float4*)h_s;
#pragma unroll
        for (int u = 0; u < 8; u++)
            hs4[tid + u * 256] = __ldcg(gh4 + tid + u * 256);
        __syncthreads();

        unsigned long long acc[16];
#pragma unroll
        for (int b = 0; b < 16; b++) acc[b] = 0ull;
#pragma unroll
        for (int u = 0; u < 16; u += 2) {
            const unsigned long long wa = w2[u], wb = w2[u + 1];
#pragma unroll
            for (int b = 0; b < 16; b++) {
                ulonglong2 hv = *reinterpret_cast<const ulonglong2*>(
                    &h_s[b * HH + seg * 32 + u * 2]);
                fma2(acc[b], wa, hv.x);
                fma2(acc[b], wb, hv.y);
            }
        }
#pragma unroll
        for (int b = 0; b < 16; b++) {
            float p = lo32(acc[b]) + hi32(acc[b]);
            p += __shfl_xor_sync(0xffffffffu, p, 16);
            if ((tid & 16) == 0)
                red[((seg >> 1) * 16 + jj) * 17 + b] = p;
        }
        __syncthreads();

        float gv = xW[((size_t)b2 * TT + t) * G4 + jrg];
#pragma unroll
        for (int s = 0; s < 8; s++) gv += red[(s * 16 + jjg) * 17 + b2];
        gpre[q2][kx2 * 16 + b2] = gv;
        __syncthreads();

        if (tid < 64) {
            int b = tid & 15, kx = tid >> 4, k = k0 + kx;
            float iv = gpre[0][kx * 16 + b];
            float fv = gpre[1][kx * 16 + b];
            float gg = gpre[2][kx * 16 + b];
            float ov = gpre[3][kx * 16 + b];
            float cold = c_s[kx][b];
            float cn = sigmoidf_(fv) * cold + sigmoidf_(iv) * tanhf(gg);
            float hn = sigmoidf_(ov) * tanhf(cn);
            c_s[kx][b] = cn;
            h_last = hn; c_last = cn;
            g_hbuf[(t + 1) & 1][b * HH + k] = hn;
            x_out[((size_t)b * TT + t) * HH + k] = hn;
        }
        gbar(bk, base + (++barn));
    }

    if (hN != nullptr && tid < 64) {
        int b = tid & 15, kx = tid >> 4, k = k0 + kx;
        hN[b * HH + k] = h_last;
        cN[b * HH + k] = c_last;
    }
}

// ---------------- host orchestration ----------------
extern "C" void kernel_launch(void* const* d_in, const int* in_sizes, int n_in,
                              void* d_out, int out_size) {
    (void)in_sizes; (void)n_in; (void)out_size;
    const int*   src     = (const int*)  d_in[0];
    const int*   tgt     = (const int*)  d_in[1];
    const float* src_emb = (const float*)d_in[2];
    const float* tgt_emb = (const float*)d_in[3];
    const float* enc_Wih = (const float*)d_in[4];
    const float* enc_Whh = (const float*)d_in[5];
    const float* enc_b   = (const float*)d_in[6];
    const float* dec_Wih = (const float*)d_in[7];
    const float* dec_Whh = (const float*)d_in[8];
    const float* dec_b   = (const float*)d_in[9];
    const float* fc_W    = (const float*)d_in[10];
    const float* fc_b    = (const float*)d_in[11];
    float* out = (float*)d_out;

    float *x0, *x1, *xw, *hN, *cN;
    __nv_bfloat16 *ahi, *alo, *whi, *wlo, *fwhi, *fwlo;
    cudaGetSymbolAddress((void**)&x0, g_x0);
    cudaGetSymbolAddress((void**)&x1, g_x1);
    cudaGetSymbolAddress((void**)&xw, g_xW);
    cudaGetSymbolAddress((void**)&hN, g_hN);
    cudaGetSymbolAddress((void**)&cN, g_cN);
    cudaGetSymbolAddress((void**)&ahi, g_ahi);
    cudaGetSymbolAddress((void**)&alo, g_alo);
    cudaGetSymbolAddress((void**)&whi, g_whi);
    cudaGetSymbolAddress((void**)&wlo, g_wlo);
    cudaGetSymbolAddress((void**)&fwhi, g_fwhi);
    cudaGetSymbolAddress((void**)&fwlo, g_fwlo);

    cudaFuncSetAttribute(gemm_mma, cudaFuncAttributeMaxDynamicSharedMemorySize, GEMM_SMEM);

    const int XN4 = NTOK * EE / 4;
    const int WN4 = G4 * EE / 4;
    const int FN4 = VT * EE / 4;

    split_kernel<<<(FN4 + 255) / 256, 256>>>(fc_W, fwhi, fwlo, FN4);

    // ---- encoder ----
    embed_kernel<<<NTOK, 128>>>(src, src_emb, x0);
    for (int l = 0; l < NLY; l++) {
        const float* xi = (l & 1) ? x1 : x0;
        float*       xo = (l & 1) ? x0 : x1;
        split_kernel<<<(XN4 + 255) / 256, 256>>>(xi, ahi, alo, XN4);
        split_kernel<<<(WN4 + 255) / 256, 256>>>(enc_Wih + (size_t)l * G4 * EE, whi, wlo, WN4);
        gemm_mma<<<dim3(G4 / 128, NTOK / 128), 256, GEMM_SMEM>>>(
            ahi, alo, whi, wlo, enc_b + l * G4, xw, G4);
        lstm_layer<<<NBLK, 256>>>(xw, enc_Whh + (size_t)l * G4 * HH, xo,
                                  nullptr, nullptr,
                                  hN + l * BB * HH, cN + l * BB * HH);
    }
    // ---- decoder ----
    embed_kernel<<<NTOK, 128>>>(tgt, tgt_emb, x0);
    for (int l = 0; l < NLY; l++) {
        const float* xi = (l & 1) ? x1 : x0;
        float*       xo = (l & 1) ? x0 : x1;
        split_kernel<<<(XN4 + 255) / 256, 256>>>(xi, ahi, alo, XN4);
        split_kernel<<<(WN4 + 255) / 256, 256>>>(dec_Wih + (size_t)l * G4 * EE, whi, wlo, WN4);
        gemm_mma<<<dim3(G4 / 128, NTOK / 128), 256, GEMM_SMEM>>>(
            ahi, alo, whi, wlo, dec_b + l * G4, xw, G4);
        lstm_layer<<<NBLK, 256>>>(xw, dec_Whh + (size_t)l * G4 * HH, xo,
                                  hN + l * BB * HH, cN + l * BB * HH,
                                  nullptr, nullptr);
    }
    // ---- vocab projection ----
    split_kernel<<<(XN4 + 255) / 256, 256>>>(x0, ahi, alo, XN4);
    gemm_mma<<<dim3(VT / 128, NTOK / 128), 256, GEMM_SMEM>>>(
        ahi, alo, fwhi, fwlo, fc_b, out, VT);
}

// round 9
// speedup vs baseline: 1.9045x; 1.0953x over previous
#include <cuda_runtime.h>
#include <cuda_bf16.h>
#include <cstdint>

#define BB   16
#define TT   128
#define EE   512
#define HH   512
#define G4   2048      // 4*H
#define NLY  4
#define VT   32000
#define NTOK (BB*TT)   // 2048
#define NBLK 128       // recurrent grid: 2 groups x 64 blocks

// ---------------- scratch (device globals; no allocs allowed) ----------------
__device__ float g_x0[NTOK*EE];
__device__ float g_x1[NTOK*EE];
__device__ float g_xW[NTOK*G4];
__device__ float g_hbuf[2][BB*HH];
__device__ float g_hN[NLY*BB*HH];
__device__ float g_cN[NLY*BB*HH];
__device__ unsigned g_flags[NBLK * 32];     // per-block flag on own 128B line
__device__ unsigned g_gen2[2 * 32];         // per-group generation word (own line)
// bf16 split buffers
__device__ __nv_bfloat16 g_ahi[NTOK*EE], g_alo[NTOK*EE];
__device__ __nv_bfloat16 g_whi[G4*EE],  g_wlo[G4*EE];
__device__ __nv_bfloat16 g_fwhi[VT*EE], g_fwlo[VT*EE];

// ---------------- fp32 -> bf16 hi/lo split ----------------
__global__ void split_kernel(const float* __restrict__ in,
                             __nv_bfloat16* __restrict__ hi,
                             __nv_bfloat16* __restrict__ lo, int n4) {
    int i = blockIdx.x * blockDim.x + threadIdx.x;
    if (i >= n4) return;
    float4 v = ((const float4*)in)[i];
    __nv_bfloat16 h[4], l[4];
    float f[4] = { v.x, v.y, v.z, v.w };
#pragma unroll
    for (int j = 0; j < 4; j++) {
        h[j] = __float2bfloat16(f[j]);
        l[j] = __float2bfloat16(f[j] - __bfloat162float(h[j]));
    }
    ((uint2*)hi)[i] = *(uint2*)h;
    ((uint2*)lo)[i] = *(uint2*)l;
}

// ---------------- mma.sync helper ----------------
__device__ __forceinline__ void mma16816(float* d, const uint32_t* a, const uint32_t* b) {
    asm volatile(
        "mma.sync.aligned.m16n8k16.row.col.f32.bf16.bf16.f32 "
        "{%0,%1,%2,%3}, {%4,%5,%6,%7}, {%8,%9}, {%0,%1,%2,%3};"
        : "+f"(d[0]), "+f"(d[1]), "+f"(d[2]), "+f"(d[3])
        : "r"(a[0]), "r"(a[1]), "r"(a[2]), "r"(a[3]), "r"(b[0]), "r"(b[1]));
}

// ---------------- bf16 split GEMM via mma.sync (unchanged from R8) ----------------
#define SMW 36
#define TILE_WORDS (128 * SMW)
__global__ __launch_bounds__(256)
void gemm_mma(const __nv_bfloat16* __restrict__ Ahi, const __nv_bfloat16* __restrict__ Alo,
              const __nv_bfloat16* __restrict__ Bhi, const __nv_bfloat16* __restrict__ Blo,
              const float* __restrict__ bias, float* __restrict__ C, int N) {
    extern __shared__ uint32_t sm[];
    uint32_t* sAhi = sm;
    uint32_t* sAlo = sm + TILE_WORDS;
    uint32_t* sBhi = sm + 2 * TILE_WORDS;
    uint32_t* sBlo = sm + 3 * TILE_WORDS;

    const int tid  = threadIdx.x;
    const int lane = tid & 31;
    const int wid  = tid >> 5;
    const int n0 = blockIdx.x * 128, m0 = blockIdx.y * 128;
    const int m0w = (wid & 1) * 64;
    const int n0w = (wid >> 1) * 32;
    const int lr = lane >> 2;
    const int lc = lane & 3;

    float acc[4][4][4];
#pragma unroll
    for (int i = 0; i < 4; i++)
#pragma unroll
        for (int j = 0; j < 4; j++)
#pragma unroll
            for (int q = 0; q < 4; q++) acc[i][j][q] = 0.f;

    for (int kc = 0; kc < 8; kc++) {
        const int k0 = kc * 64;
        {
            const __nv_bfloat16* srcs[4] = {
                Ahi + (size_t)m0 * 512 + k0, Alo + (size_t)m0 * 512 + k0,
                Bhi + (size_t)n0 * 512 + k0, Blo + (size_t)n0 * 512 + k0 };
            uint32_t* dsts[4] = { sAhi, sAlo, sBhi, sBlo };
#pragma unroll
            for (int tl = 0; tl < 4; tl++) {
#pragma unroll
                for (int i = 0; i < 4; i++) {
                    int lin = tid + i * 256;
                    int row = lin >> 3, g = lin & 7;
                    uint4 v = *(const uint4*)(srcs[tl] + (size_t)row * 512 + g * 8);
                    uint32_t* d = dsts[tl] + row * SMW + g * 4;
                    *(uint2*)d       = make_uint2(v.x, v.y);
                    *(uint2*)(d + 2) = make_uint2(v.z, v.w);
                }
            }
        }
        __syncthreads();

#pragma unroll
        for (int kk = 0; kk < 4; kk++) {
            const int kw = kk * 8 + lc;
            uint32_t ah[4][4], al[4][4], bh[4][2], bl[4][2];
#pragma unroll
            for (int mt = 0; mt < 4; mt++) {
                int r = m0w + mt * 16 + lr;
                ah[mt][0] = sAhi[r * SMW + kw];
                ah[mt][1] = sAhi[(r + 8) * SMW + kw];
                ah[mt][2] = sAhi[r * SMW + kw + 4];
                ah[mt][3] = sAhi[(r + 8) * SMW + kw + 4];
                al[mt][0] = sAlo[r * SMW + kw];
                al[mt][1] = sAlo[(r + 8) * SMW + kw];
                al[mt][2] = sAlo[r * SMW + kw + 4];
                al[mt][3] = sAlo[(r + 8) * SMW + kw + 4];
            }
#pragma unroll
            for (int nt = 0; nt < 4; nt++) {
                int n = n0w + nt * 8 + lr;
                bh[nt][0] = sBhi[n * SMW + kw];
                bh[nt][1] = sBhi[n * SMW + kw + 4];
                bl[nt][0] = sBlo[n * SMW + kw];
                bl[nt][1] = sBlo[n * SMW + kw + 4];
            }
#pragma unroll
            for (int mt = 0; mt < 4; mt++)
#pragma unroll
                for (int nt = 0; nt < 4; nt++) {
                    mma16816(acc[mt][nt], ah[mt], bh[nt]);
                    mma16816(acc[mt][nt], ah[mt], bl[nt]);
                    mma16816(acc[mt][nt], al[mt], bh[nt]);
                }
        }
        __syncthreads();
    }

#pragma unroll
    for (int nt = 0; nt < 4; nt++) {
        int col = n0 + n0w + nt * 8 + lc * 2;
        float2 bv = *(const float2*)&bias[col];
#pragma unroll
        for (int mt = 0; mt < 4; mt++) {
            int r = m0 + m0w + mt * 16 + lr;
            *(float2*)&C[(size_t)r * N + col] =
                make_float2(acc[mt][nt][0] + bv.x, acc[mt][nt][1] + bv.y);
            *(float2*)&C[(size_t)(r + 8) * N + col] =
                make_float2(acc[mt][nt][2] + bv.x, acc[mt][nt][3] + bv.y);
        }
    }
}
#define GEMM_SMEM (4 * TILE_WORDS * 4)

// ---------------- embedding gather ----------------
__global__ void embed_kernel(const int* __restrict__ idx,
                             const float* __restrict__ emb,
                             float* __restrict__ out) {
    int row = blockIdx.x;
    int v   = idx[row];
    const float4* s = (const float4*)(emb + (size_t)v * EE);
    float4*       d = (float4*)(out + (size_t)row * EE);
    d[threadIdx.x] = s[threadIdx.x];
}

// ---------------- packed f32x2 helpers ----------------
__device__ __forceinline__ void fma2(unsigned long long &acc,
                                     unsigned long long a, unsigned long long b) {
    asm("fma.rn.f32x2 %0, %1, %2, %0;" : "+l"(acc) : "l"(a), "l"(b));
}
__device__ __forceinline__ float lo32(unsigned long long v) { return __uint_as_float((unsigned)v); }
__device__ __forceinline__ float hi32(unsigned long long v) { return __uint_as_float((unsigned)(v >> 32)); }

// ---------------- per-group grid barrier (64 blocks per group) ----------------
// Same proven volatile-ld/st master-aggregator as R6, but scoped to a group:
// group master = block grp*64, polls its 64 flags, publishes g_gen2[grp].
__device__ __forceinline__ void gbar2(int bk, int grp, unsigned target) {
    __syncthreads();
    if (threadIdx.x == 0) {
        __threadfence();
        *(volatile unsigned*)&g_flags[bk * 32] = target;
    }
    if (bk == grp * 64) {
        if (threadIdx.x < 32) {
            const int b0 = grp * 64;
            for (;;) {
                unsigned v0 = *(volatile unsigned*)&g_flags[(b0 + threadIdx.x) * 32];
                unsigned v1 = *(volatile unsigned*)&g_flags[(b0 + 32 + threadIdx.x) * 32];
                bool ok = ((int)(v0 - target) >= 0) && ((int)(v1 - target) >= 0);
                if (__all_sync(0xffffffffu, ok)) break;
            }
            if (threadIdx.x == 0) {
                __threadfence();
                *(volatile unsigned*)&g_gen2[grp * 32] = target;
            }
        }
    } else {
        if (threadIdx.x == 0) {
            while ((int)(*(volatile unsigned*)&g_gen2[grp * 32] - target) < 0) {}
            __threadfence();
        }
    }
    __syncthreads();
}

__device__ __forceinline__ float sigmoidf_(float x) { return 1.0f / (1.0f + expf(-x)); }

// ---------------- persistent LSTM layer: 2 batch-groups x 64 blocks ----------------
// Group grp handles batches [grp*8, grp*8+8). Block lbk (0..63) owns k-slice
// [lbk*8, lbk*8+8) -> 32 Whh rows (4 gates x 8 k) in registers (64 f/thread).
// Thread (jj = tid&31 row, seg = tid>>5 k-seg of 64): full broadcast LDS.
__global__ __launch_bounds__(256)
void lstm_layer(const float* __restrict__ xW, const float* __restrict__ Whh,
                float* __restrict__ x_out,
                const float* __restrict__ h0, const float* __restrict__ c0,
                float* __restrict__ hN, float* __restrict__ cN) {
    __shared__ float h_s[8 * HH];           // 16KB: 8 local batches x 512
    __shared__ float red[8 * 8 * 33];       // [b][seg][row(33 pad)] 8.4KB
    __shared__ float gpre[4][72];           // [gate][kx*9 + b]
    __shared__ float c_s[8][8];             // [kx][b]
    __shared__ unsigned s_base;

    const int tid = threadIdx.x;
    const int bk  = blockIdx.x;             // 0..127
    const int grp = bk >> 6;                // batch group
    const int lbk = bk & 63;
    const int k0  = lbk * 8;
    const int jj  = tid & 31;               // row 0..31
    const int seg = tid >> 5;               // k-segment (== warp id)
    const int gate = jj >> 3;
    const int jrow = gate * 512 + k0 + (jj & 7);

    if (tid == 0) s_base = *(volatile unsigned*)&g_flags[bk * 32];

    // Whh slice -> registers: 64 floats = 32 f32x2 pairs
    unsigned long long w2[32];
    {
        const float* wr = Whh + (size_t)jrow * 512 + seg * 64;
#pragma unroll
        for (int u = 0; u < 32; u++)
            w2[u] = *reinterpret_cast<const unsigned long long*>(wr + u * 2);
    }

    // gather mapping: thread -> (row gr, batch gb); warp == batch
    const int gr = tid & 31, gb = tid >> 5;
    const int ggate = gr >> 3, gkx = gr & 7;
    const size_t xw_base = ((size_t)(grp * 8 + gb) * TT) * G4
                         + ggate * 512 + k0 + gkx;

    float h_last = 0.f, c_last = 0.f;
    if (tid < 64) {
        int b = tid & 7, kx = tid >> 3;
        int gbat = grp * 8 + b, k = k0 + kx;
        c_s[kx][b] = c0 ? c0[gbat * HH + k] : 0.f;
        g_hbuf[0][gbat * HH + k] = h0 ? h0[gbat * HH + k] : 0.f;
    }
    __syncthreads();
    unsigned base = s_base;
    unsigned barn = 0;
    gbar2(bk, grp, base + (++barn));        // publish initial h/c

    for (int t = 0; t < TT; t++) {
        // prefetch this step's xW early (hide L2 latency behind GEMV)
        float gv = __ldg(&xW[xw_base + (size_t)t * G4]);

        // load group's h slice (8 batches x 512 = 4K floats) into smem
        const float4* gh4 = (const float4*)g_hbuf[t & 1] + grp * 1024;
        float4* hs4 = (float4*)h_s;
#pragma unroll
        for (int u = 0; u < 4; u++)
            hs4[tid + u * 256] = __ldcg(gh4 + tid + u * 256);
        __syncthreads();

        // partial dot: acc[b] over this thread's 64 k
        unsigned long long acc[8];
#pragma unroll
        for (int b = 0; b < 8; b++) acc[b] = 0ull;
#pragma unroll
        for (int u = 0; u < 32; u += 2) {
            const unsigned long long wa = w2[u], wb = w2[u + 1];
#pragma unroll
            for (int b = 0; b < 8; b++) {
                ulonglong2 hv = *reinterpret_cast<const ulonglong2*>(
                    &h_s[b * HH + seg * 64 + u * 2]);
                fma2(acc[b], wa, hv.x);
                fma2(acc[b], wb, hv.y);
            }
        }
        // store per-seg partials: red[b][seg][jj]
#pragma unroll
        for (int b = 0; b < 8; b++)
            red[(b * 8 + seg) * 33 + jj] = lo32(acc[b]) + hi32(acc[b]);
        __syncthreads();

        // gather: full dot + xW -> gate pre-activation
#pragma unroll
        for (int s = 0; s < 8; s++) gv += red[(gb * 8 + s) * 33 + gr];
        gpre[ggate][gkx * 9 + gb] = gv;
        __syncthreads();

        // pointwise update: 64 threads own (8 k x 8 b) states
        if (tid < 64) {
            int b = tid & 7, kx = tid >> 3;
            int gbat = grp * 8 + b, k = k0 + kx;
            float iv = gpre[0][kx * 9 + b];
            float fv = gpre[1][kx * 9 + b];
            float gg = gpre[2][kx * 9 + b];
            float ov = gpre[3][kx * 9 + b];
            float cold = c_s[kx][b];
            float cn = sigmoidf_(fv) * cold + sigmoidf_(iv) * tanhf(gg);
            float hn = sigmoidf_(ov) * tanhf(cn);
            c_s[kx][b] = cn;
            h_last = hn; c_last = cn;
            g_hbuf[(t + 1) & 1][gbat * HH + k] = hn;
            x_out[((size_t)gbat * TT + t) * HH + k] = hn;
        }
        gbar2(bk, grp, base + (++barn));
    }

    if (hN != nullptr && tid < 64) {
        int b = tid & 7, kx = tid >> 3;
        int gbat = grp * 8 + b, k = k0 + kx;
        hN[gbat * HH + k] = h_last;
        cN[gbat * HH + k] = c_last;
    }
}

// ---------------- host orchestration ----------------
extern "C" void kernel_launch(void* const* d_in, const int* in_sizes, int n_in,
                              void* d_out, int out_size) {
    (void)in_sizes; (void)n_in; (void)out_size;
    const int*   src     = (const int*)  d_in[0];
    const int*   tgt     = (const int*)  d_in[1];
    const float* src_emb = (const float*)d_in[2];
    const float* tgt_emb = (const float*)d_in[3];
    const float* enc_Wih = (const float*)d_in[4];
    const float* enc_Whh = (const float*)d_in[5];
    const float* enc_b   = (const float*)d_in[6];
    const float* dec_Wih = (const float*)d_in[7];
    const float* dec_Whh = (const float*)d_in[8];
    const float* dec_b   = (const float*)d_in[9];
    const float* fc_W    = (const float*)d_in[10];
    const float* fc_b    = (const float*)d_in[11];
    float* out = (float*)d_out;

    float *x0, *x1, *xw, *hN, *cN;
    __nv_bfloat16 *ahi, *alo, *whi, *wlo, *fwhi, *fwlo;
    cudaGetSymbolAddress((void**)&x0, g_x0);
    cudaGetSymbolAddress((void**)&x1, g_x1);
    cudaGetSymbolAddress((void**)&xw, g_xW);
    cudaGetSymbolAddress((void**)&hN, g_hN);
    cudaGetSymbolAddress((void**)&cN, g_cN);
    cudaGetSymbolAddress((void**)&ahi, g_ahi);
    cudaGetSymbolAddress((void**)&alo, g_alo);
    cudaGetSymbolAddress((void**)&whi, g_whi);
    cudaGetSymbolAddress((void**)&wlo, g_wlo);
    cudaGetSymbolAddress((void**)&fwhi, g_fwhi);
    cudaGetSymbolAddress((void**)&fwlo, g_fwlo);

    cudaFuncSetAttribute(gemm_mma, cudaFuncAttributeMaxDynamicSharedMemorySize, GEMM_SMEM);

    const int XN4 = NTOK * EE / 4;
    const int WN4 = G4 * EE / 4;
    const int FN4 = VT * EE / 4;

    split_kernel<<<(FN4 + 255) / 256, 256>>>(fc_W, fwhi, fwlo, FN4);

    // ---- encoder ----
    embed_kernel<<<NTOK, 128>>>(src, src_emb, x0);
    for (int l = 0; l < NLY; l++) {
        const float* xi = (l & 1) ? x1 : x0;
        float*       xo = (l & 1) ? x0 : x1;
        split_kernel<<<(XN4 + 255) / 256, 256>>>(xi, ahi, alo, XN4);
        split_kernel<<<(WN4 + 255) / 256, 256>>>(enc_Wih + (size_t)l * G4 * EE, whi, wlo, WN4);
        gemm_mma<<<dim3(G4 / 128, NTOK / 128), 256, GEMM_SMEM>>>(
            ahi, alo, whi, wlo, enc_b + l * G4, xw, G4);
        lstm_layer<<<NBLK, 256>>>(xw, enc_Whh + (size_t)l * G4 * HH, xo,
                                  nullptr, nullptr,
                                  hN + l * BB * HH, cN + l * BB * HH);
    }
    // ---- decoder ----
    embed_kernel<<<NTOK, 128>>>(tgt, tgt_emb, x0);
    for (int l = 0; l < NLY; l++) {
        const float* xi = (l & 1) ? x1 : x0;
        float*       xo = (l & 1) ? x0 : x1;
        split_kernel<<<(XN4 + 255) / 256, 256>>>(xi, ahi, alo, XN4);
        split_kernel<<<(WN4 + 255) / 256, 256>>>(dec_Wih + (size_t)l * G4 * EE, whi, wlo, WN4);
        gemm_mma<<<dim3(G4 / 128, NTOK / 128), 256, GEMM_SMEM>>>(
            ahi, alo, whi, wlo, dec_b + l * G4, xw, G4);
        lstm_layer<<<NBLK, 256>>>(xw, dec_Whh + (size_t)l * G4 * HH, xo,
                                  hN + l * BB * HH, cN + l * BB * HH,
                                  nullptr, nullptr);
    }
    // ---- vocab projection ----
    split_kernel<<<(XN4 + 255) / 256, 256>>>(x0, ahi, alo, XN4);
    gemm_mma<<<dim3(VT / 128, NTOK / 128), 256, GEMM_SMEM>>>(
        ahi, alo, fwhi, fwlo, fc_b, out, VT);
}